// round 12
// baseline (speedup 1.0000x reference)
#include <cuda_runtime.h>
#include <cuda_fp16.h>
#include <cstdint>

// ---------------- problem constants ----------------
static constexpr int Bsz = 16384;
static constexpr int SMEM_DYN = 104 * 1024 + 1024;  // layers: 32+8+32+32 K; phase0: 80K

// ---------------- device scratch ----------------
__device__ float  g_Anum[32 * 256];
__device__ float  g_c[256];
__device__ __half g_W1ph[8 * 8 * 4 * 64 * 64];    // [l][kc][kb][n64][k64] swizzled fp16
__device__ __half g_W2ph[8 * 8 * 8 * 32 * 64];    // [l][kc][piece][n32][k64]
__device__ __half g_Wfph[65 * 256 * 64];          // [chunk][n256][k64] (chunk0 = numeric+zeros)

// ---------------- PTX helpers ----------------
__device__ __forceinline__ uint32_t sm32(const void* p) {
    uint32_t a;
    asm("{ .reg .u64 t; cvta.to.shared.u64 t, %1; cvt.u32.u64 %0, t; }" : "=r"(a) : "l"(p));
    return a;
}
__device__ __forceinline__ void cpa16(uint32_t dst, const void* src) {
    asm volatile("cp.async.cg.shared.global [%0], [%1], 16;" :: "r"(dst), "l"(src));
}
#define CPA_COMMIT() asm volatile("cp.async.commit_group;" ::: "memory")
#define CPA_WAIT(n)  asm volatile("cp.async.wait_group %0;" :: "n"(n) : "memory")

__device__ __forceinline__ void ldm4(uint32_t (&r)[4], uint32_t addr) {
    asm volatile("ldmatrix.sync.aligned.m8n8.x4.shared.b16 {%0,%1,%2,%3}, [%4];"
                 : "=r"(r[0]), "=r"(r[1]), "=r"(r[2]), "=r"(r[3]) : "r"(addr));
}
__device__ __forceinline__ void mma_f16(float (&d)[4], const uint32_t (&a)[4],
                                        uint32_t b0, uint32_t b1) {
    asm volatile("mma.sync.aligned.m16n8k16.row.col.f32.f16.f16.f32 "
                 "{%0,%1,%2,%3}, {%4,%5,%6,%7}, {%8,%9}, {%0,%1,%2,%3};"
                 : "+f"(d[0]), "+f"(d[1]), "+f"(d[2]), "+f"(d[3])
                 : "r"(a[0]), "r"(a[1]), "r"(a[2]), "r"(a[3]), "r"(b0), "r"(b1));
}
__device__ __forceinline__ uint32_t f2h2(float lo, float hi) {
    uint32_t r;
    asm("cvt.rn.f16x2.f32 %0, %1, %2;" : "=r"(r) : "f"(hi), "f"(lo));
    return r;
}
__device__ __forceinline__ void st1s(uint32_t a, uint32_t v) {
    asm volatile("st.shared.b32 [%0], %1;" :: "r"(a), "r"(v));
}
__device__ __forceinline__ void st4s(uint32_t a, uint32_t x, uint32_t y, uint32_t z, uint32_t w) {
    asm volatile("st.shared.v4.b32 [%0], {%1,%2,%3,%4};" :: "r"(a), "r"(x), "r"(y), "r"(z), "r"(w));
}
__device__ __forceinline__ int swzk(int j, int n) {
    return (((j >> 3) ^ (n & 7)) << 3) | (j & 7);
}

// ---------------- single merged prep kernel ----------------
static constexpr int NW1 = 524288, NW2 = 524288, NWFC = 64 * 256 * 32;
__global__ __launch_bounds__(256) void prep_all(
    const float* __restrict__ w_num, const float* __restrict__ b_num,
    const float* __restrict__ W_first, const float* __restrict__ b_first,
    const float* __restrict__ W1s, const float* __restrict__ W2s)
{
    const float* Wcat = W_first + (size_t)8192 * 256;
    int cta = blockIdx.x, tid = threadIdx.x;

    if (cta == 0) {
        // ---- Anum fold (per-f chains; order identical to R11) + chunk0 pack ----
        int j = tid;
        for (int f0 = 0; f0 < 32; f0 += 4) {
            float a0 = 0.f, a1 = 0.f, a2 = 0.f, a3 = 0.f;
            const float* base = W_first + (size_t)f0 * 256 * 256 + j;
            const float* wn = w_num + f0 * 256;
            for (int d = 0; d < 256; d++) {
                size_t off = (size_t)d * 256;
                a0 = fmaf(wn[d],       base[off],                a0);
                a1 = fmaf(wn[256 + d], base[off + 65536],        a1);
                a2 = fmaf(wn[512 + d], base[off + 131072],       a2);
                a3 = fmaf(wn[768 + d], base[off + 196608],       a3);
            }
            g_Anum[(f0 + 0) * 256 + j] = a0;
            g_Anum[(f0 + 1) * 256 + j] = a1;
            g_Anum[(f0 + 2) * 256 + j] = a2;
            g_Anum[(f0 + 3) * 256 + j] = a3;
        }
        __syncthreads();
        for (int i = tid; i < 8192; i += 256) {
            int j2 = (i & 31) * 2, n = i >> 5;
            int k = swzk(j2, n);
            float v0 = (k < 32) ? g_Anum[k * 256 + n] : 0.f;
            float v1 = (k < 32) ? g_Anum[(k + 1) * 256 + n] : 0.f;
            ((__half2*)g_Wfph)[i] = __floats2half2_rn(v0, v1);
        }
    } else if (cta == 1) {
        // ---- c vector: 8-way ILP over k ----
        int j = tid;
        float a[8] = {b_first[j], 0.f, 0.f, 0.f, 0.f, 0.f, 0.f, 0.f};
        for (int k = 0; k < 8192; k += 8) {
#pragma unroll
            for (int u = 0; u < 8; u++)
                a[u] = fmaf(b_num[k + u], W_first[(size_t)(k + u) * 256 + j], a[u]);
        }
        g_c[j] = ((a[0] + a[1]) + (a[2] + a[3])) + ((a[4] + a[5]) + (a[6] + a[7]));
    } else {
        // ---- grid-stride weight packing across CTAs 2..255 ----
        int stride = 254 * 256;
        for (int t = (cta - 2) * 256 + tid; t < NW1 + NW2 + NWFC; t += stride) {
            if (t < NW1) {
                int i = t;
                int j = (i & 31) * 2, n = (i >> 5) & 63, kb = (i >> 11) & 3,
                    kc = (i >> 13) & 7, l = i >> 16;
                int k = swzk(j, n);
                const float* s = W1s + (size_t)(l * 256 + kb * 64 + k) * 512 + kc * 64 + n;
                ((__half2*)g_W1ph)[i] = __floats2half2_rn(s[0], s[512]);
            } else if (t < NW1 + NW2) {
                int i = t - NW1;
                int j = (i & 31) * 2, n = (i >> 5) & 31, p = (i >> 10) & 7,
                    kc = (i >> 13) & 7, l = i >> 16;
                int k = swzk(j, n);
                const float* s = W2s + (size_t)(l * 512 + kc * 64 + k) * 256 + p * 32 + n;
                ((__half2*)g_W2ph)[i] = __floats2half2_rn(s[0], s[256]);
            } else {
                int u = t - NW1 - NW2;              // chunks 1..64
                int j = (u & 31) * 2, n = (u >> 5) & 255, c = u >> 13;
                int k = swzk(j, n);
                const float* s = Wcat + (size_t)(c * 64 + k) * 256 + n;
                ((__half2*)g_Wfph)[8192 + u] = __floats2half2_rn(s[0], s[256]);
            }
        }
    }
}

// =====================================================================
// Persistent fused network kernel (fp16 operands, fp32 accum).
// One CTA = 64 rows, 256 threads, occ 2. Full 32KB weight buffers,
// 2 syncs per kc, loads fully overlapped with the opposite GEMM.
// =====================================================================
__global__ __launch_bounds__(256, 2) void fused_net(
    const float* __restrict__ xnum, const int* __restrict__ xidx,
    const float* __restrict__ cemb,
    const float* __restrict__ b1g, const float* __restrict__ b2g,
    const float* __restrict__ lng, const float* __restrict__ lnbet,
    const float* __restrict__ gf,  const float* __restrict__ betf,
    const float* __restrict__ Wh,  const float* __restrict__ bh,
    float* __restrict__ out)
{
    extern __shared__ float dsm[];
    __shared__ float red_s[64 * 4], red_q[64 * 4];
    __shared__ int s_xidx[64 * 16];
    uint32_t raw  = sm32(dsm);
    uint32_t base = (raw + 1023u) & ~1023u;
    const uint32_t LNB = base;
    const uint32_t TCH = base + 32768u;
    const uint32_t B0  = base + 40960u;
    const uint32_t B1  = base + 73728u;
    const uint32_t P0A = base;
    const uint32_t P0B = base + 16384u;

    int tid = threadIdx.x, wid = tid >> 5, lane = tid & 31;
    int bm = blockIdx.x * 64;
    int warp_m = wid & 1, warp_n = wid >> 1;
    int wm1 = wid & 3,    wn1 = wid >> 2;
    int lr = lane & 7, lh = (lane >> 3) & 1, lg = lane >> 4;

    float hreg[16][4];
#pragma unroll
    for (int t = 0; t < 16; t++)
#pragma unroll
        for (int q = 0; q < 4; q++) hreg[t][q] = 0.f;

    for (int i = tid; i < 64 * 16; i += 256) s_xidx[i] = xidx[bm * 16 + i];
    __syncthreads();

    // ================= Phase 0: first GEMM, 65 chunks of 64 k =================
    {
        int ar = tid >> 2, aq = tid & 3;
        float4 R4[4];
        auto ldgA = [&](int c) {
            if (c == 0) {
                if (aq < 2) {
                    const float4* s = (const float4*)(xnum + (size_t)(bm + ar) * 32 + aq * 16);
#pragma unroll
                    for (int i = 0; i < 4; i++) R4[i] = s[i];
                } else {
#pragma unroll
                    for (int i = 0; i < 4; i++) R4[i] = make_float4(0.f, 0.f, 0.f, 0.f);
                }
            } else {
                int cc = c - 1, f = cc >> 2, d0 = (cc & 3) << 6;
                const float4* s = (const float4*)(cemb + (size_t)s_xidx[ar * 16 + f] * 256 + d0 + aq * 16);
#pragma unroll
                for (int i = 0; i < 4; i++) R4[i] = s[i];
            }
        };
        auto stsA = [&](int b) {
            uint32_t bufa = P0A + (uint32_t)b * 8192u + (uint32_t)ar * 128u;
#pragma unroll
            for (int t = 0; t < 2; t++) {
                int g = aq * 2 + t;
                uint32_t a = bufa + (uint32_t)((g ^ (ar & 7)) << 4);
                st4s(a, f2h2(R4[2 * t].x, R4[2 * t].y), f2h2(R4[2 * t].z, R4[2 * t].w),
                        f2h2(R4[2 * t + 1].x, R4[2 * t + 1].y), f2h2(R4[2 * t + 1].z, R4[2 * t + 1].w));
            }
        };
        auto cpB = [&](int c, int b) {
            const float4* src = (const float4*)(g_Wfph + (size_t)c * 16384) + tid;
            uint32_t Bd = P0B + (uint32_t)b * 32768u + (uint32_t)tid * 16u;
#pragma unroll
            for (int i = 0; i < 8; i++) cpa16(Bd + (uint32_t)i * 4096u, src + i * 256);
            CPA_COMMIT();
        };

        ldgA(0);
        cpB(0, 0); cpB(1, 1);
#pragma unroll 1
        for (int c = 0; c <= 64; c++) {
            int b = c & 1;
            stsA(b);
            if (c < 64) ldgA(c + 1);
            if (c + 1 <= 64) CPA_WAIT(1); else CPA_WAIT(0);
            __syncthreads();
            uint32_t Ab = P0A + (uint32_t)b * 8192u;
            uint32_t Bb = P0B + (uint32_t)b * 32768u;
#pragma unroll
            for (int s = 0; s < 4; s++) {
                int g = s * 2 + lg;
                uint32_t af[2][4];
#pragma unroll
                for (int i = 0; i < 2; i++) {
                    int R = warp_m * 32 + i * 16 + lr + lh * 8;
                    ldm4(af[i], Ab + (uint32_t)(R * 128 + ((g ^ (R & 7)) << 4)));
                }
                uint32_t bf[8][2];
#pragma unroll
                for (int p = 0; p < 4; p++) {
                    int n = warp_n * 64 + p * 16 + lr + lh * 8;
                    uint32_t t4[4];
                    ldm4(t4, Bb + (uint32_t)(n * 128 + ((g ^ (n & 7)) << 4)));
                    bf[2 * p][0] = t4[0]; bf[2 * p][1] = t4[2];
                    bf[2 * p + 1][0] = t4[1]; bf[2 * p + 1][1] = t4[3];
                }
#pragma unroll
                for (int i = 0; i < 2; i++)
#pragma unroll
                    for (int j = 0; j < 8; j++)
                        mma_f16(hreg[i * 8 + j], af[i], bf[j][0], bf[j][1]);
            }
            __syncthreads();
            if (c + 2 <= 64) cpB(c + 2, b);
        }
#pragma unroll
        for (int i = 0; i < 2; i++)
#pragma unroll
            for (int j = 0; j < 8; j++) {
                int col = warp_n * 64 + j * 8 + (lane & 3) * 2;
                float b0 = g_c[col], b1 = g_c[col + 1];
                hreg[i * 8 + j][0] += b0; hreg[i * 8 + j][1] += b1;
                hreg[i * 8 + j][2] += b0; hreg[i * 8 + j][3] += b1;
            }
    }

    // ---- full 32KB weight loaders ----
    auto issueWf = [&](const __half* W, int kc, uint32_t B) {
        const float4* src = (const float4*)(W + (size_t)kc * 16384) + tid;
#pragma unroll
        for (int i = 0; i < 8; i++) cpa16(B + (uint32_t)(tid * 16 + i * 4096), src + i * 256);
        CPA_COMMIT();
    };

    // ---- LN from hreg -> LNB (fp16) ----
    auto do_ln = [&](const float* gam, const float* bet) {
        float rs_[4] = {0.f, 0.f, 0.f, 0.f}, rq_[4] = {0.f, 0.f, 0.f, 0.f};
#pragma unroll
        for (int i = 0; i < 2; i++)
#pragma unroll
            for (int j = 0; j < 8; j++) {
                float v0 = hreg[i * 8 + j][0], v1 = hreg[i * 8 + j][1];
                float v2 = hreg[i * 8 + j][2], v3 = hreg[i * 8 + j][3];
                rs_[i * 2 + 0] += v0 + v1;  rq_[i * 2 + 0] += v0 * v0 + v1 * v1;
                rs_[i * 2 + 1] += v2 + v3;  rq_[i * 2 + 1] += v2 * v2 + v3 * v3;
            }
#pragma unroll
        for (int t = 0; t < 4; t++)
#pragma unroll
            for (int o = 1; o <= 2; o <<= 1) {
                rs_[t] += __shfl_xor_sync(0xffffffffu, rs_[t], o);
                rq_[t] += __shfl_xor_sync(0xffffffffu, rq_[t], o);
            }
        if ((lane & 3) == 0) {
#pragma unroll
            for (int i = 0; i < 2; i++)
#pragma unroll
                for (int h = 0; h < 2; h++) {
                    int rloc = warp_m * 32 + i * 16 + h * 8 + (lane >> 2);
                    red_s[rloc * 4 + warp_n] = rs_[i * 2 + h];
                    red_q[rloc * 4 + warp_n] = rq_[i * 2 + h];
                }
        }
        __syncthreads();
#pragma unroll
        for (int i = 0; i < 2; i++)
#pragma unroll
            for (int h = 0; h < 2; h++) {
                int rloc = warp_m * 32 + i * 16 + h * 8 + (lane >> 2);
                float s = red_s[rloc * 4 + 0] + red_s[rloc * 4 + 1]
                        + red_s[rloc * 4 + 2] + red_s[rloc * 4 + 3];
                float q = red_q[rloc * 4 + 0] + red_q[rloc * 4 + 1]
                        + red_q[rloc * 4 + 2] + red_q[rloc * 4 + 3];
                float mu = s * (1.f / 256.f);
                float rinv = rsqrtf(q * (1.f / 256.f) - mu * mu + 1e-5f);
#pragma unroll
                for (int j = 0; j < 8; j++) {
                    int col = warp_n * 64 + j * 8 + (lane & 3) * 2;
                    float y0 = (hreg[i * 8 + j][h * 2 + 0] - mu) * rinv * gam[col]     + bet[col];
                    float y1 = (hreg[i * 8 + j][h * 2 + 1] - mu) * rinv * gam[col + 1] + bet[col + 1];
                    int kcol = col & 63, kb = col >> 6, gg = kcol >> 3;
                    uint32_t addr = LNB + (uint32_t)(kb * 8192 + rloc * 128
                                   + ((gg ^ (rloc & 7)) << 4) + (kcol & 7) * 2);
                    st1s(addr, f2h2(y0, y1));
                }
            }
        __syncthreads();
    };

    // GEMM1 full: 4 kb blocks from one 32KB buffer
    float a1[4][4];
    auto g1full = [&](uint32_t B) {
#pragma unroll
        for (int kb = 0; kb < 4; kb++) {
#pragma unroll
            for (int s = 0; s < 4; s++) {
                int g = s * 2 + lg;
                uint32_t af[4];
                int R = wm1 * 16 + lr + lh * 8;
                ldm4(af, LNB + (uint32_t)(kb * 8192 + R * 128 + ((g ^ (R & 7)) << 4)));
                uint32_t bf[4][2];
#pragma unroll
                for (int pp = 0; pp < 2; pp++) {
                    int n = wn1 * 32 + pp * 16 + lr + lh * 8;
                    uint32_t t4[4];
                    ldm4(t4, B + (uint32_t)(kb * 8192 + n * 128 + ((g ^ (n & 7)) << 4)));
                    bf[2 * pp][0] = t4[0]; bf[2 * pp][1] = t4[2];
                    bf[2 * pp + 1][0] = t4[1]; bf[2 * pp + 1][1] = t4[3];
                }
#pragma unroll
                for (int j = 0; j < 4; j++) mma_f16(a1[j], af, bf[j][0], bf[j][1]);
            }
        }
    };
    // GEMM2 full: A fragments hoisted out of the piece loop
    auto g2full = [&](uint32_t B) {
#pragma unroll
        for (int s = 0; s < 4; s++) {
            int g = s * 2 + lg;
            uint32_t af[2][4];
#pragma unroll
            for (int i = 0; i < 2; i++) {
                int R = warp_m * 32 + i * 16 + lr + lh * 8;
                ldm4(af[i], TCH + (uint32_t)(R * 128 + ((g ^ (R & 7)) << 4)));
            }
#pragma unroll
            for (int p = 0; p < 2; p++) {
                uint32_t Bp = B + (uint32_t)(2 * warp_n + p) * 4096u;
                uint32_t bf[4][2];
#pragma unroll
                for (int pp = 0; pp < 2; pp++) {
                    int nl = pp * 16 + lr + lh * 8;
                    uint32_t t4[4];
                    ldm4(t4, Bp + (uint32_t)(nl * 128 + ((g ^ (nl & 7)) << 4)));
                    bf[2 * pp][0] = t4[0]; bf[2 * pp][1] = t4[2];
                    bf[2 * pp + 1][0] = t4[1]; bf[2 * pp + 1][1] = t4[3];
                }
#pragma unroll
                for (int i = 0; i < 2; i++)
#pragma unroll
                    for (int jj = 0; jj < 4; jj++)
                        mma_f16(hreg[i * 8 + p * 4 + jj], af[i], bf[jj][0], bf[jj][1]);
            }
        }
    };

    issueWf(g_W1ph, 0, B0);

    // ================= 8 residual layers =================
#pragma unroll 1
    for (int l = 0; l < 8; l++) {
        do_ln(lng + l * 256, lnbet + l * 256);
        const __half* W1 = g_W1ph + (size_t)l * 8 * 16384;
        const __half* W2 = g_W2ph + (size_t)l * 8 * 16384;
        const float*  b1 = b1g + l * 512;
#pragma unroll 1
        for (int kc = 0; kc < 8; kc++) {
#pragma unroll
            for (int j = 0; j < 4; j++)
#pragma unroll
                for (int q = 0; q < 4; q++) a1[j][q] = 0.f;
            // ---- S1: wait W1(kc); issue W2(kc)->B1; GEMM1; relu+bias -> TCH ----
            CPA_WAIT(0);
            __syncthreads();
            issueWf(W2, kc, B1);
            g1full(B0);
#pragma unroll
            for (int j = 0; j < 4; j++) {
                int row0 = wm1 * 16 + (lane >> 2);
                int colL = wn1 * 32 + j * 8 + (lane & 3) * 2;
                int gc = kc * 64 + colL;
                float bb0 = b1[gc], bb1 = b1[gc + 1];
                uint32_t plo = f2h2(fmaxf(a1[j][0] + bb0, 0.f), fmaxf(a1[j][1] + bb1, 0.f));
                uint32_t phi = f2h2(fmaxf(a1[j][2] + bb0, 0.f), fmaxf(a1[j][3] + bb1, 0.f));
                int gg = colL >> 3;
                uint32_t sw = (uint32_t)(((gg ^ (row0 & 7)) << 4) + (colL & 7) * 2);
                st1s(TCH + (uint32_t)(row0 * 128) + sw, plo);
                st1s(TCH + (uint32_t)((row0 + 8) * 128) + sw, phi);
            }
            // ---- S2: wait W2(kc); issue W1(kc+1)->B0; GEMM2 ----
            CPA_WAIT(0);
            __syncthreads();
            if (kc < 7)     issueWf(W1, kc + 1, B0);
            else if (l < 7) issueWf(g_W1ph + (size_t)(l + 1) * 8 * 16384, 0, B0);
            g2full(B1);
        }
        const float* b2 = b2g + l * 256;
#pragma unroll
        for (int i = 0; i < 2; i++)
#pragma unroll
            for (int j = 0; j < 8; j++) {
                int col = warp_n * 64 + j * 8 + (lane & 3) * 2;
                float b0 = b2[col], b1v = b2[col + 1];
                hreg[i * 8 + j][0] += b0;  hreg[i * 8 + j][1] += b1v;
                hreg[i * 8 + j][2] += b0;  hreg[i * 8 + j][3] += b1v;
            }
    }

    // ================= final LN + head =================
    {
        float rs_[4] = {0.f, 0.f, 0.f, 0.f}, rq_[4] = {0.f, 0.f, 0.f, 0.f};
#pragma unroll
        for (int i = 0; i < 2; i++)
#pragma unroll
            for (int j = 0; j < 8; j++) {
                float v0 = hreg[i * 8 + j][0], v1 = hreg[i * 8 + j][1];
                float v2 = hreg[i * 8 + j][2], v3 = hreg[i * 8 + j][3];
                rs_[i * 2 + 0] += v0 + v1;  rq_[i * 2 + 0] += v0 * v0 + v1 * v1;
                rs_[i * 2 + 1] += v2 + v3;  rq_[i * 2 + 1] += v2 * v2 + v3 * v3;
            }
#pragma unroll
        for (int t = 0; t < 4; t++)
#pragma unroll
            for (int o = 1; o <= 2; o <<= 1) {
                rs_[t] += __shfl_xor_sync(0xffffffffu, rs_[t], o);
                rq_[t] += __shfl_xor_sync(0xffffffffu, rq_[t], o);
            }
        if ((lane & 3) == 0) {
#pragma unroll
            for (int i = 0; i < 2; i++)
#pragma unroll
                for (int h = 0; h < 2; h++) {
                    int rloc = warp_m * 32 + i * 16 + h * 8 + (lane >> 2);
                    red_s[rloc * 4 + warp_n] = rs_[i * 2 + h];
                    red_q[rloc * 4 + warp_n] = rq_[i * 2 + h];
                }
        }
        __syncthreads();
        float hd0[4] = {0.f, 0.f, 0.f, 0.f}, hd1[4] = {0.f, 0.f, 0.f, 0.f};
#pragma unroll
        for (int i = 0; i < 2; i++)
#pragma unroll
            for (int h = 0; h < 2; h++) {
                int rloc = warp_m * 32 + i * 16 + h * 8 + (lane >> 2);
                float s = red_s[rloc * 4 + 0] + red_s[rloc * 4 + 1]
                        + red_s[rloc * 4 + 2] + red_s[rloc * 4 + 3];
                float q = red_q[rloc * 4 + 0] + red_q[rloc * 4 + 1]
                        + red_q[rloc * 4 + 2] + red_q[rloc * 4 + 3];
                float mu = s * (1.f / 256.f);
                float rinv = rsqrtf(q * (1.f / 256.f) - mu * mu + 1e-5f);
#pragma unroll
                for (int j = 0; j < 8; j++) {
                    int col = warp_n * 64 + j * 8 + (lane & 3) * 2;
                    float y0 = (hreg[i * 8 + j][h * 2 + 0] - mu) * rinv * gf[col]     + betf[col];
                    float y1 = (hreg[i * 8 + j][h * 2 + 1] - mu) * rinv * gf[col + 1] + betf[col + 1];
                    hd0[i * 2 + h] += y0 * Wh[col * 2 + 0] + y1 * Wh[col * 2 + 2];
                    hd1[i * 2 + h] += y0 * Wh[col * 2 + 1] + y1 * Wh[col * 2 + 3];
                }
            }
#pragma unroll
        for (int t = 0; t < 4; t++)
#pragma unroll
            for (int o = 1; o <= 2; o <<= 1) {
                hd0[t] += __shfl_xor_sync(0xffffffffu, hd0[t], o);
                hd1[t] += __shfl_xor_sync(0xffffffffu, hd1[t], o);
            }
        __syncthreads();
        if ((lane & 3) == 0) {
#pragma unroll
            for (int i = 0; i < 2; i++)
#pragma unroll
                for (int h = 0; h < 2; h++) {
                    int rloc = warp_m * 32 + i * 16 + h * 8 + (lane >> 2);
                    red_s[rloc * 4 + warp_n] = hd0[i * 2 + h];
                    red_q[rloc * 4 + warp_n] = hd1[i * 2 + h];
                }
        }
        __syncthreads();
        if (tid < 64) {
            float s0 = red_s[tid * 4 + 0] + red_s[tid * 4 + 1]
                     + red_s[tid * 4 + 2] + red_s[tid * 4 + 3];
            float s1 = red_q[tid * 4 + 0] + red_q[tid * 4 + 1]
                     + red_q[tid * 4 + 2] + red_q[tid * 4 + 3];
            out[(bm + tid) * 2 + 0] = s0 + bh[0];
            out[(bm + tid) * 2 + 1] = s1 + bh[1];
        }
    }
}

// ---------------- launch (2 kernels) ----------------
extern "C" void kernel_launch(void* const* d_in, const int* in_sizes, int n_in,
                              void* d_out, int out_size) {
    const float* x_num   = (const float*)d_in[0];
    const int*   xidx    = (const int*)  d_in[1];
    const float* w_num   = (const float*)d_in[2];
    const float* b_num   = (const float*)d_in[3];
    const float* cat_emb = (const float*)d_in[4];
    const float* W_first = (const float*)d_in[5];
    const float* b_first = (const float*)d_in[6];
    const float* ln_g    = (const float*)d_in[7];
    const float* ln_b    = (const float*)d_in[8];
    const float* W1s     = (const float*)d_in[9];
    const float* b1s     = (const float*)d_in[10];
    const float* W2s     = (const float*)d_in[11];
    const float* b2s     = (const float*)d_in[12];
    const float* g_f     = (const float*)d_in[13];
    const float* beta_f  = (const float*)d_in[14];
    const float* W_head  = (const float*)d_in[15];
    const float* b_head  = (const float*)d_in[16];

    cudaFuncSetAttribute(fused_net, cudaFuncAttributeMaxDynamicSharedMemorySize, SMEM_DYN);

    prep_all<<<256, 256>>>(w_num, b_num, W_first, b_first, W1s, W2s);

    fused_net<<<256, 256, SMEM_DYN>>>(
        x_num, xidx, cat_emb, b1s, b2s, ln_g, ln_b,
        g_f, beta_f, W_head, b_head, (float*)d_out);
}

// round 13
// speedup vs baseline: 2.1175x; 2.1175x over previous
#include <cuda_runtime.h>
#include <cuda_fp16.h>
#include <cstdint>

// ---------------- problem constants ----------------
static constexpr int Bsz = 16384;
static constexpr int SMEM_DYN = 104 * 1024 + 1024;  // layers: 32+8+32+32 K; phase0: 80K

// ---------------- device scratch ----------------
__device__ float  g_Anum[32 * 256];
__device__ float  g_c[256];
__device__ float  g_cpart[32 * 256];
__device__ __half g_W1ph[8 * 8 * 4 * 64 * 64];    // [l][kc][kb][n64][k64] swizzled fp16
__device__ __half g_W2ph[8 * 8 * 8 * 32 * 64];    // [l][kc][piece][n32][k64]
__device__ __half g_Wfph[65 * 256 * 64];          // [chunk][n256][k64] (chunk0 = numeric+zeros)

// ---------------- PTX helpers ----------------
__device__ __forceinline__ uint32_t sm32(const void* p) {
    uint32_t a;
    asm("{ .reg .u64 t; cvta.to.shared.u64 t, %1; cvt.u32.u64 %0, t; }" : "=r"(a) : "l"(p));
    return a;
}
__device__ __forceinline__ void cpa16(uint32_t dst, const void* src) {
    asm volatile("cp.async.cg.shared.global [%0], [%1], 16;" :: "r"(dst), "l"(src));
}
#define CPA_COMMIT() asm volatile("cp.async.commit_group;" ::: "memory")
#define CPA_WAIT(n)  asm volatile("cp.async.wait_group %0;" :: "n"(n) : "memory")

__device__ __forceinline__ void ldm4(uint32_t (&r)[4], uint32_t addr) {
    asm volatile("ldmatrix.sync.aligned.m8n8.x4.shared.b16 {%0,%1,%2,%3}, [%4];"
                 : "=r"(r[0]), "=r"(r[1]), "=r"(r[2]), "=r"(r[3]) : "r"(addr));
}
__device__ __forceinline__ void mma_f16(float (&d)[4], const uint32_t (&a)[4],
                                        uint32_t b0, uint32_t b1) {
    asm volatile("mma.sync.aligned.m16n8k16.row.col.f32.f16.f16.f32 "
                 "{%0,%1,%2,%3}, {%4,%5,%6,%7}, {%8,%9}, {%0,%1,%2,%3};"
                 : "+f"(d[0]), "+f"(d[1]), "+f"(d[2]), "+f"(d[3])
                 : "r"(a[0]), "r"(a[1]), "r"(a[2]), "r"(a[3]), "r"(b0), "r"(b1));
}
__device__ __forceinline__ uint32_t f2h2(float lo, float hi) {
    uint32_t r;
    asm("cvt.rn.f16x2.f32 %0, %1, %2;" : "=r"(r) : "f"(hi), "f"(lo));
    return r;
}
__device__ __forceinline__ void st1s(uint32_t a, uint32_t v) {
    asm volatile("st.shared.b32 [%0], %1;" :: "r"(a), "r"(v));
}
__device__ __forceinline__ void st4s(uint32_t a, uint32_t x, uint32_t y, uint32_t z, uint32_t w) {
    asm volatile("st.shared.v4.b32 [%0], {%1,%2,%3,%4};" :: "r"(a), "r"(x), "r"(y), "r"(z), "r"(w));
}
__device__ __forceinline__ int swzk(int j, int n) {
    return (((j >> 3) ^ (n & 7)) << 3) | (j & 7);
}

// ---------------- prep kernel 1: parallel folds (64 CTAs) ----------------
// blocks 0-31: A_num fold; blocks 32-63: c partials (identical to R11 ordering)
__global__ void prep_fold(const float* __restrict__ w_num, const float* __restrict__ b_num,
                          const float* __restrict__ W_first) {
    int j = threadIdx.x;
    if (blockIdx.x < 32) {
        int f = blockIdx.x;
        const float* Wf = W_first + (size_t)f * 256 * 256 + j;
        const float* wn = w_num + f * 256;
        float acc = 0.f;
        for (int d = 0; d < 256; d++) acc = fmaf(wn[d], Wf[(size_t)d * 256], acc);
        g_Anum[f * 256 + j] = acc;
    } else {
        int b = blockIdx.x - 32;
        const float* W = W_first + (size_t)b * 256 * 256 + j;
        const float* bn = b_num + b * 256;
        float acc = 0.f;
        for (int k = 0; k < 256; k++) acc = fmaf(bn[k], W[(size_t)k * 256], acc);
        g_cpart[b * 256 + j] = acc;
    }
}

// ---------------- prep kernel 2: pack everything + c2 reduction ----------------
static constexpr int NW1 = 524288, NW2 = 524288, NWF = 65 * 256 * 32;
__global__ void pack_all(const float* __restrict__ W1s, const float* __restrict__ W2s,
                         const float* __restrict__ Wcat, const float* __restrict__ b_first) {
    // c2 reduction in CTA 0 (trivial: 32 adds per thread)
    if (blockIdx.x == 0) {
        int j = threadIdx.x;
        float acc = b_first[j];
        for (int b = 0; b < 32; b++) acc += g_cpart[b * 256 + j];
        g_c[j] = acc;
    }
    for (int t = blockIdx.x * blockDim.x + threadIdx.x; t < NW1 + NW2 + NWF;
         t += gridDim.x * blockDim.x) {
        if (t < NW1) {
            int i = t;
            int j = (i & 31) * 2, n = (i >> 5) & 63, kb = (i >> 11) & 3, kc = (i >> 13) & 7, l = i >> 16;
            int k = swzk(j, n);
            const float* s = W1s + (size_t)(l * 256 + kb * 64 + k) * 512 + kc * 64 + n;
            ((__half2*)g_W1ph)[i] = __floats2half2_rn(s[0], s[512]);
        } else if (t < NW1 + NW2) {
            int i = t - NW1;
            int j = (i & 31) * 2, n = (i >> 5) & 31, p = (i >> 10) & 7, kc = (i >> 13) & 7, l = i >> 16;
            int k = swzk(j, n);
            const float* s = W2s + (size_t)(l * 512 + kc * 64 + k) * 256 + p * 32 + n;
            ((__half2*)g_W2ph)[i] = __floats2half2_rn(s[0], s[256]);
        } else {
            int i = t - NW1 - NW2;
            int j = (i & 31) * 2, n = (i >> 5) & 255, c = i >> 13;
            int k = swzk(j, n);
            float v0, v1;
            if (c == 0) {
                v0 = (k < 32) ? g_Anum[k * 256 + n] : 0.f;
                v1 = (k < 32) ? g_Anum[(k + 1) * 256 + n] : 0.f;
            } else {
                const float* s = Wcat + (size_t)((c - 1) * 64 + k) * 256 + n;
                v0 = s[0]; v1 = s[256];
            }
            ((__half2*)g_Wfph)[i] = __floats2half2_rn(v0, v1);
        }
    }
}

// =====================================================================
// Persistent fused network kernel (fp16 operands, fp32 accum).
// One CTA = 64 rows, 256 threads, occ 2. Full 32KB weight buffers,
// 2 syncs per kc, loads fully overlapped with the opposite GEMM.
// =====================================================================
__global__ __launch_bounds__(256, 2) void fused_net(
    const float* __restrict__ xnum, const int* __restrict__ xidx,
    const float* __restrict__ cemb,
    const float* __restrict__ b1g, const float* __restrict__ b2g,
    const float* __restrict__ lng, const float* __restrict__ lnbet,
    const float* __restrict__ gf,  const float* __restrict__ betf,
    const float* __restrict__ Wh,  const float* __restrict__ bh,
    float* __restrict__ out)
{
    extern __shared__ float dsm[];
    __shared__ float red_s[64 * 4], red_q[64 * 4];
    __shared__ int s_xidx[64 * 16];
    uint32_t raw  = sm32(dsm);
    uint32_t base = (raw + 1023u) & ~1023u;
    const uint32_t LNB = base;
    const uint32_t TCH = base + 32768u;
    const uint32_t B0  = base + 40960u;
    const uint32_t B1  = base + 73728u;
    const uint32_t P0A = base;
    const uint32_t P0B = base + 16384u;

    int tid = threadIdx.x, wid = tid >> 5, lane = tid & 31;
    int bm = blockIdx.x * 64;
    int warp_m = wid & 1, warp_n = wid >> 1;
    int wm1 = wid & 3,    wn1 = wid >> 2;
    int lr = lane & 7, lh = (lane >> 3) & 1, lg = lane >> 4;

    float hreg[16][4];
#pragma unroll
    for (int t = 0; t < 16; t++)
#pragma unroll
        for (int q = 0; q < 4; q++) hreg[t][q] = 0.f;

    for (int i = tid; i < 64 * 16; i += 256) s_xidx[i] = xidx[bm * 16 + i];
    __syncthreads();

    // ================= Phase 0: first GEMM, 65 chunks of 64 k =================
    {
        int ar = tid >> 2, aq = tid & 3;
        float4 R4[4];
        auto ldgA = [&](int c) {
            if (c == 0) {
                if (aq < 2) {
                    const float4* s = (const float4*)(xnum + (size_t)(bm + ar) * 32 + aq * 16);
#pragma unroll
                    for (int i = 0; i < 4; i++) R4[i] = s[i];
                } else {
#pragma unroll
                    for (int i = 0; i < 4; i++) R4[i] = make_float4(0.f, 0.f, 0.f, 0.f);
                }
            } else {
                int cc = c - 1, f = cc >> 2, d0 = (cc & 3) << 6;
                const float4* s = (const float4*)(cemb + (size_t)s_xidx[ar * 16 + f] * 256 + d0 + aq * 16);
#pragma unroll
                for (int i = 0; i < 4; i++) R4[i] = s[i];
            }
        };
        auto stsA = [&](int b) {
            uint32_t bufa = P0A + (uint32_t)b * 8192u + (uint32_t)ar * 128u;
#pragma unroll
            for (int t = 0; t < 2; t++) {
                int g = aq * 2 + t;
                uint32_t a = bufa + (uint32_t)((g ^ (ar & 7)) << 4);
                st4s(a, f2h2(R4[2 * t].x, R4[2 * t].y), f2h2(R4[2 * t].z, R4[2 * t].w),
                        f2h2(R4[2 * t + 1].x, R4[2 * t + 1].y), f2h2(R4[2 * t + 1].z, R4[2 * t + 1].w));
            }
        };
        auto cpB = [&](int c, int b) {
            const float4* src = (const float4*)(g_Wfph + (size_t)c * 16384) + tid;
            uint32_t Bd = P0B + (uint32_t)b * 32768u + (uint32_t)tid * 16u;
#pragma unroll
            for (int i = 0; i < 8; i++) cpa16(Bd + (uint32_t)i * 4096u, src + i * 256);
            CPA_COMMIT();
        };

        ldgA(0);
        cpB(0, 0); cpB(1, 1);
#pragma unroll 1
        for (int c = 0; c <= 64; c++) {
            int b = c & 1;
            stsA(b);
            if (c < 64) ldgA(c + 1);
            if (c + 1 <= 64) CPA_WAIT(1); else CPA_WAIT(0);
            __syncthreads();
            uint32_t Ab = P0A + (uint32_t)b * 8192u;
            uint32_t Bb = P0B + (uint32_t)b * 32768u;
#pragma unroll
            for (int s = 0; s < 4; s++) {
                int g = s * 2 + lg;
                uint32_t af[2][4];
#pragma unroll
                for (int i = 0; i < 2; i++) {
                    int R = warp_m * 32 + i * 16 + lr + lh * 8;
                    ldm4(af[i], Ab + (uint32_t)(R * 128 + ((g ^ (R & 7)) << 4)));
                }
                uint32_t bf[8][2];
#pragma unroll
                for (int p = 0; p < 4; p++) {
                    int n = warp_n * 64 + p * 16 + lr + lh * 8;
                    uint32_t t4[4];
                    ldm4(t4, Bb + (uint32_t)(n * 128 + ((g ^ (n & 7)) << 4)));
                    bf[2 * p][0] = t4[0]; bf[2 * p][1] = t4[2];
                    bf[2 * p + 1][0] = t4[1]; bf[2 * p + 1][1] = t4[3];
                }
#pragma unroll
                for (int i = 0; i < 2; i++)
#pragma unroll
                    for (int j = 0; j < 8; j++)
                        mma_f16(hreg[i * 8 + j], af[i], bf[j][0], bf[j][1]);
            }
            __syncthreads();
            if (c + 2 <= 64) cpB(c + 2, b);
        }
#pragma unroll
        for (int i = 0; i < 2; i++)
#pragma unroll
            for (int j = 0; j < 8; j++) {
                int col = warp_n * 64 + j * 8 + (lane & 3) * 2;
                float b0 = g_c[col], b1 = g_c[col + 1];
                hreg[i * 8 + j][0] += b0; hreg[i * 8 + j][1] += b1;
                hreg[i * 8 + j][2] += b0; hreg[i * 8 + j][3] += b1;
            }
    }

    // ---- full 32KB weight loaders ----
    auto issueWf = [&](const __half* W, int kc, uint32_t B) {
        const float4* src = (const float4*)(W + (size_t)kc * 16384) + tid;
#pragma unroll
        for (int i = 0; i < 8; i++) cpa16(B + (uint32_t)(tid * 16 + i * 4096), src + i * 256);
        CPA_COMMIT();
    };

    // ---- LN from hreg -> LNB (fp16) ----
    auto do_ln = [&](const float* gam, const float* bet) {
        float rs_[4] = {0.f, 0.f, 0.f, 0.f}, rq_[4] = {0.f, 0.f, 0.f, 0.f};
#pragma unroll
        for (int i = 0; i < 2; i++)
#pragma unroll
            for (int j = 0; j < 8; j++) {
                float v0 = hreg[i * 8 + j][0], v1 = hreg[i * 8 + j][1];
                float v2 = hreg[i * 8 + j][2], v3 = hreg[i * 8 + j][3];
                rs_[i * 2 + 0] += v0 + v1;  rq_[i * 2 + 0] += v0 * v0 + v1 * v1;
                rs_[i * 2 + 1] += v2 + v3;  rq_[i * 2 + 1] += v2 * v2 + v3 * v3;
            }
#pragma unroll
        for (int t = 0; t < 4; t++)
#pragma unroll
            for (int o = 1; o <= 2; o <<= 1) {
                rs_[t] += __shfl_xor_sync(0xffffffffu, rs_[t], o);
                rq_[t] += __shfl_xor_sync(0xffffffffu, rq_[t], o);
            }
        if ((lane & 3) == 0) {
#pragma unroll
            for (int i = 0; i < 2; i++)
#pragma unroll
                for (int h = 0; h < 2; h++) {
                    int rloc = warp_m * 32 + i * 16 + h * 8 + (lane >> 2);
                    red_s[rloc * 4 + warp_n] = rs_[i * 2 + h];
                    red_q[rloc * 4 + warp_n] = rq_[i * 2 + h];
                }
        }
        __syncthreads();
#pragma unroll
        for (int i = 0; i < 2; i++)
#pragma unroll
            for (int h = 0; h < 2; h++) {
                int rloc = warp_m * 32 + i * 16 + h * 8 + (lane >> 2);
                float s = red_s[rloc * 4 + 0] + red_s[rloc * 4 + 1]
                        + red_s[rloc * 4 + 2] + red_s[rloc * 4 + 3];
                float q = red_q[rloc * 4 + 0] + red_q[rloc * 4 + 1]
                        + red_q[rloc * 4 + 2] + red_q[rloc * 4 + 3];
                float mu = s * (1.f / 256.f);
                float rinv = rsqrtf(q * (1.f / 256.f) - mu * mu + 1e-5f);
#pragma unroll
                for (int j = 0; j < 8; j++) {
                    int col = warp_n * 64 + j * 8 + (lane & 3) * 2;
                    float y0 = (hreg[i * 8 + j][h * 2 + 0] - mu) * rinv * gam[col]     + bet[col];
                    float y1 = (hreg[i * 8 + j][h * 2 + 1] - mu) * rinv * gam[col + 1] + bet[col + 1];
                    int kcol = col & 63, kb = col >> 6, gg = kcol >> 3;
                    uint32_t addr = LNB + (uint32_t)(kb * 8192 + rloc * 128
                                   + ((gg ^ (rloc & 7)) << 4) + (kcol & 7) * 2);
                    st1s(addr, f2h2(y0, y1));
                }
            }
        __syncthreads();
    };

    // GEMM1 full: 4 kb blocks from one 32KB buffer
    float a1[4][4];
    auto g1full = [&](uint32_t B) {
#pragma unroll
        for (int kb = 0; kb < 4; kb++) {
#pragma unroll
            for (int s = 0; s < 4; s++) {
                int g = s * 2 + lg;
                uint32_t af[4];
                int R = wm1 * 16 + lr + lh * 8;
                ldm4(af, LNB + (uint32_t)(kb * 8192 + R * 128 + ((g ^ (R & 7)) << 4)));
                uint32_t bf[4][2];
#pragma unroll
                for (int pp = 0; pp < 2; pp++) {
                    int n = wn1 * 32 + pp * 16 + lr + lh * 8;
                    uint32_t t4[4];
                    ldm4(t4, B + (uint32_t)(kb * 8192 + n * 128 + ((g ^ (n & 7)) << 4)));
                    bf[2 * pp][0] = t4[0]; bf[2 * pp][1] = t4[2];
                    bf[2 * pp + 1][0] = t4[1]; bf[2 * pp + 1][1] = t4[3];
                }
#pragma unroll
                for (int j = 0; j < 4; j++) mma_f16(a1[j], af, bf[j][0], bf[j][1]);
            }
        }
    };
    // GEMM2 full: A fragments hoisted out of the piece loop
    auto g2full = [&](uint32_t B) {
#pragma unroll
        for (int s = 0; s < 4; s++) {
            int g = s * 2 + lg;
            uint32_t af[2][4];
#pragma unroll
            for (int i = 0; i < 2; i++) {
                int R = warp_m * 32 + i * 16 + lr + lh * 8;
                ldm4(af[i], TCH + (uint32_t)(R * 128 + ((g ^ (R & 7)) << 4)));
            }
#pragma unroll
            for (int p = 0; p < 2; p++) {
                uint32_t Bp = B + (uint32_t)(2 * warp_n + p) * 4096u;
                uint32_t bf[4][2];
#pragma unroll
                for (int pp = 0; pp < 2; pp++) {
                    int nl = pp * 16 + lr + lh * 8;
                    uint32_t t4[4];
                    ldm4(t4, Bp + (uint32_t)(nl * 128 + ((g ^ (nl & 7)) << 4)));
                    bf[2 * pp][0] = t4[0]; bf[2 * pp][1] = t4[2];
                    bf[2 * pp + 1][0] = t4[1]; bf[2 * pp + 1][1] = t4[3];
                }
#pragma unroll
                for (int i = 0; i < 2; i++)
#pragma unroll
                    for (int jj = 0; jj < 4; jj++)
                        mma_f16(hreg[i * 8 + p * 4 + jj], af[i], bf[jj][0], bf[jj][1]);
            }
        }
    };

    issueWf(g_W1ph, 0, B0);

    // ================= 8 residual layers =================
#pragma unroll 1
    for (int l = 0; l < 8; l++) {
        do_ln(lng + l * 256, lnbet + l * 256);
        const __half* W1 = g_W1ph + (size_t)l * 8 * 16384;
        const __half* W2 = g_W2ph + (size_t)l * 8 * 16384;
        const float*  b1 = b1g + l * 512;
#pragma unroll 1
        for (int kc = 0; kc < 8; kc++) {
#pragma unroll
            for (int j = 0; j < 4; j++)
#pragma unroll
                for (int q = 0; q < 4; q++) a1[j][q] = 0.f;
            // ---- S1: wait W1(kc); issue W2(kc)->B1; GEMM1; relu+bias -> TCH ----
            CPA_WAIT(0);
            __syncthreads();
            issueWf(W2, kc, B1);
            g1full(B0);
#pragma unroll
            for (int j = 0; j < 4; j++) {
                int row0 = wm1 * 16 + (lane >> 2);
                int colL = wn1 * 32 + j * 8 + (lane & 3) * 2;
                int gc = kc * 64 + colL;
                float bb0 = b1[gc], bb1 = b1[gc + 1];
                uint32_t plo = f2h2(fmaxf(a1[j][0] + bb0, 0.f), fmaxf(a1[j][1] + bb1, 0.f));
                uint32_t phi = f2h2(fmaxf(a1[j][2] + bb0, 0.f), fmaxf(a1[j][3] + bb1, 0.f));
                int gg = colL >> 3;
                uint32_t sw = (uint32_t)(((gg ^ (row0 & 7)) << 4) + (colL & 7) * 2);
                st1s(TCH + (uint32_t)(row0 * 128) + sw, plo);
                st1s(TCH + (uint32_t)((row0 + 8) * 128) + sw, phi);
            }
            // ---- S2: wait W2(kc); issue W1(kc+1)->B0; GEMM2 ----
            CPA_WAIT(0);
            __syncthreads();
            if (kc < 7)     issueWf(W1, kc + 1, B0);
            else if (l < 7) issueWf(g_W1ph + (size_t)(l + 1) * 8 * 16384, 0, B0);
            g2full(B1);
        }
        const float* b2 = b2g + l * 256;
#pragma unroll
        for (int i = 0; i < 2; i++)
#pragma unroll
            for (int j = 0; j < 8; j++) {
                int col = warp_n * 64 + j * 8 + (lane & 3) * 2;
                float b0 = b2[col], b1v = b2[col + 1];
                hreg[i * 8 + j][0] += b0;  hreg[i * 8 + j][1] += b1v;
                hreg[i * 8 + j][2] += b0;  hreg[i * 8 + j][3] += b1v;
            }
    }

    // ================= final LN + head =================
    {
        float rs_[4] = {0.f, 0.f, 0.f, 0.f}, rq_[4] = {0.f, 0.f, 0.f, 0.f};
#pragma unroll
        for (int i = 0; i < 2; i++)
#pragma unroll
            for (int j = 0; j < 8; j++) {
                float v0 = hreg[i * 8 + j][0], v1 = hreg[i * 8 + j][1];
                float v2 = hreg[i * 8 + j][2], v3 = hreg[i * 8 + j][3];
                rs_[i * 2 + 0] += v0 + v1;  rq_[i * 2 + 0] += v0 * v0 + v1 * v1;
                rs_[i * 2 + 1] += v2 + v3;  rq_[i * 2 + 1] += v2 * v2 + v3 * v3;
            }
#pragma unroll
        for (int t = 0; t < 4; t++)
#pragma unroll
            for (int o = 1; o <= 2; o <<= 1) {
                rs_[t] += __shfl_xor_sync(0xffffffffu, rs_[t], o);
                rq_[t] += __shfl_xor_sync(0xffffffffu, rq_[t], o);
            }
        if ((lane & 3) == 0) {
#pragma unroll
            for (int i = 0; i < 2; i++)
#pragma unroll
                for (int h = 0; h < 2; h++) {
                    int rloc = warp_m * 32 + i * 16 + h * 8 + (lane >> 2);
                    red_s[rloc * 4 + warp_n] = rs_[i * 2 + h];
                    red_q[rloc * 4 + warp_n] = rq_[i * 2 + h];
                }
        }
        __syncthreads();
        float hd0[4] = {0.f, 0.f, 0.f, 0.f}, hd1[4] = {0.f, 0.f, 0.f, 0.f};
#pragma unroll
        for (int i = 0; i < 2; i++)
#pragma unroll
            for (int h = 0; h < 2; h++) {
                int rloc = warp_m * 32 + i * 16 + h * 8 + (lane >> 2);
                float s = red_s[rloc * 4 + 0] + red_s[rloc * 4 + 1]
                        + red_s[rloc * 4 + 2] + red_s[rloc * 4 + 3];
                float q = red_q[rloc * 4 + 0] + red_q[rloc * 4 + 1]
                        + red_q[rloc * 4 + 2] + red_q[rloc * 4 + 3];
                float mu = s * (1.f / 256.f);
                float rinv = rsqrtf(q * (1.f / 256.f) - mu * mu + 1e-5f);
#pragma unroll
                for (int j = 0; j < 8; j++) {
                    int col = warp_n * 64 + j * 8 + (lane & 3) * 2;
                    float y0 = (hreg[i * 8 + j][h * 2 + 0] - mu) * rinv * gf[col]     + betf[col];
                    float y1 = (hreg[i * 8 + j][h * 2 + 1] - mu) * rinv * gf[col + 1] + betf[col + 1];
                    hd0[i * 2 + h] += y0 * Wh[col * 2 + 0] + y1 * Wh[col * 2 + 2];
                    hd1[i * 2 + h] += y0 * Wh[col * 2 + 1] + y1 * Wh[col * 2 + 3];
                }
            }
#pragma unroll
        for (int t = 0; t < 4; t++)
#pragma unroll
            for (int o = 1; o <= 2; o <<= 1) {
                hd0[t] += __shfl_xor_sync(0xffffffffu, hd0[t], o);
                hd1[t] += __shfl_xor_sync(0xffffffffu, hd1[t], o);
            }
        __syncthreads();
        if ((lane & 3) == 0) {
#pragma unroll
            for (int i = 0; i < 2; i++)
#pragma unroll
                for (int h = 0; h < 2; h++) {
                    int rloc = warp_m * 32 + i * 16 + h * 8 + (lane >> 2);
                    red_s[rloc * 4 + warp_n] = hd0[i * 2 + h];
                    red_q[rloc * 4 + warp_n] = hd1[i * 2 + h];
                }
        }
        __syncthreads();
        if (tid < 64) {
            float s0 = red_s[tid * 4 + 0] + red_s[tid * 4 + 1]
                     + red_s[tid * 4 + 2] + red_s[tid * 4 + 3];
            float s1 = red_q[tid * 4 + 0] + red_q[tid * 4 + 1]
                     + red_q[tid * 4 + 2] + red_q[tid * 4 + 3];
            out[(bm + tid) * 2 + 0] = s0 + bh[0];
            out[(bm + tid) * 2 + 1] = s1 + bh[1];
        }
    }
}

// ---------------- launch (3 kernels) ----------------
extern "C" void kernel_launch(void* const* d_in, const int* in_sizes, int n_in,
                              void* d_out, int out_size) {
    const float* x_num   = (const float*)d_in[0];
    const int*   xidx    = (const int*)  d_in[1];
    const float* w_num   = (const float*)d_in[2];
    const float* b_num   = (const float*)d_in[3];
    const float* cat_emb = (const float*)d_in[4];
    const float* W_first = (const float*)d_in[5];
    const float* b_first = (const float*)d_in[6];
    const float* ln_g    = (const float*)d_in[7];
    const float* ln_b    = (const float*)d_in[8];
    const float* W1s     = (const float*)d_in[9];
    const float* b1s     = (const float*)d_in[10];
    const float* W2s     = (const float*)d_in[11];
    const float* b2s     = (const float*)d_in[12];
    const float* g_f     = (const float*)d_in[13];
    const float* beta_f  = (const float*)d_in[14];
    const float* W_head  = (const float*)d_in[15];
    const float* b_head  = (const float*)d_in[16];

    cudaFuncSetAttribute(fused_net, cudaFuncAttributeMaxDynamicSharedMemorySize, SMEM_DYN);

    prep_fold<<<64, 256>>>(w_num, b_num, W_first);
    pack_all<<<1024, 256>>>(W1s, W2s, W_first + (size_t)8192 * 256, b_first);

    fused_net<<<256, 256, SMEM_DYN>>>(
        x_num, xidx, cat_emb, b1s, b2s, ln_g, ln_b,
        g_f, beta_f, W_head, b_head, (float*)d_out);
}

// round 14
// speedup vs baseline: 2.1642x; 1.0221x over previous
#include <cuda_runtime.h>
#include <cuda_fp16.h>
#include <cstdint>

// ---------------- problem constants ----------------
static constexpr int Bsz = 16384;
static constexpr int SMEM_DYN = 104 * 1024 + 1024;  // layers: 32+8+32+32 K; phase0: 80K

// ---------------- device scratch ----------------
__device__ float  g_Apart[128 * 256];             // Anum partials: [f*4+q][j]
__device__ float  g_c[256];
__device__ float  g_cpart[128 * 256];             // c partials: [kslice][j]
__device__ __half g_W1ph[8 * 8 * 4 * 64 * 64];    // [l][kc][kb][n64][k64] swizzled fp16
__device__ __half g_W2ph[8 * 8 * 8 * 32 * 64];    // [l][kc][piece][n32][k64]
__device__ __half g_Wfph[65 * 256 * 64];          // [chunk][n256][k64] (chunk0 = numeric+zeros)

// ---------------- PTX helpers ----------------
__device__ __forceinline__ uint32_t sm32(const void* p) {
    uint32_t a;
    asm("{ .reg .u64 t; cvta.to.shared.u64 t, %1; cvt.u32.u64 %0, t; }" : "=r"(a) : "l"(p));
    return a;
}
__device__ __forceinline__ void cpa16(uint32_t dst, const void* src) {
    asm volatile("cp.async.cg.shared.global [%0], [%1], 16;" :: "r"(dst), "l"(src));
}
#define CPA_COMMIT() asm volatile("cp.async.commit_group;" ::: "memory")
#define CPA_WAIT(n)  asm volatile("cp.async.wait_group %0;" :: "n"(n) : "memory")

__device__ __forceinline__ void ldm4(uint32_t (&r)[4], uint32_t addr) {
    asm volatile("ldmatrix.sync.aligned.m8n8.x4.shared.b16 {%0,%1,%2,%3}, [%4];"
                 : "=r"(r[0]), "=r"(r[1]), "=r"(r[2]), "=r"(r[3]) : "r"(addr));
}
__device__ __forceinline__ void mma_f16(float (&d)[4], const uint32_t (&a)[4],
                                        uint32_t b0, uint32_t b1) {
    asm volatile("mma.sync.aligned.m16n8k16.row.col.f32.f16.f16.f32 "
                 "{%0,%1,%2,%3}, {%4,%5,%6,%7}, {%8,%9}, {%0,%1,%2,%3};"
                 : "+f"(d[0]), "+f"(d[1]), "+f"(d[2]), "+f"(d[3])
                 : "r"(a[0]), "r"(a[1]), "r"(a[2]), "r"(a[3]), "r"(b0), "r"(b1));
}
__device__ __forceinline__ uint32_t f2h2(float lo, float hi) {
    uint32_t r;
    asm("cvt.rn.f16x2.f32 %0, %1, %2;" : "=r"(r) : "f"(hi), "f"(lo));
    return r;
}
__device__ __forceinline__ void st1s(uint32_t a, uint32_t v) {
    asm volatile("st.shared.b32 [%0], %1;" :: "r"(a), "r"(v));
}
__device__ __forceinline__ void st4s(uint32_t a, uint32_t x, uint32_t y, uint32_t z, uint32_t w) {
    asm volatile("st.shared.v4.b32 [%0], {%1,%2,%3,%4};" :: "r"(a), "r"(x), "r"(y), "r"(z), "r"(w));
}
__device__ __forceinline__ int swzk(int j, int n) {
    return (((j >> 3) ^ (n & 7)) << 3) | (j & 7);
}

// ---------------- prep kernel 1: parallel folds (256 CTAs, 64-step chains) ----
__global__ void prep_fold(const float* __restrict__ w_num, const float* __restrict__ b_num,
                          const float* __restrict__ W_first) {
    int j = threadIdx.x;
    if (blockIdx.x < 128) {
        int f = blockIdx.x >> 2, q = blockIdx.x & 3;
        const float* Wf = W_first + ((size_t)f * 256 + q * 64) * 256 + j;
        const float* wn = w_num + f * 256 + q * 64;
        float acc = 0.f;
        for (int d = 0; d < 64; d++) acc = fmaf(wn[d], Wf[(size_t)d * 256], acc);
        g_Apart[blockIdx.x * 256 + j] = acc;
    } else {
        int b = blockIdx.x - 128;                  // 64-k slice
        const float* W = W_first + (size_t)b * 64 * 256 + j;
        const float* bn = b_num + b * 64;
        float acc = 0.f;
        for (int k = 0; k < 64; k++) acc = fmaf(bn[k], W[(size_t)k * 256], acc);
        g_cpart[b * 256 + j] = acc;
    }
}

// ---------------- prep kernel 2: pack everything + reductions ----------------
static constexpr int NW1 = 524288, NW2 = 524288, NWF = 65 * 256 * 32;
__global__ void pack_all(const float* __restrict__ W1s, const float* __restrict__ W2s,
                         const float* __restrict__ Wcat, const float* __restrict__ b_first) {
    // c reduction in CTA 0
    if (blockIdx.x == 0) {
        int j = threadIdx.x;
        float acc = b_first[j];
        for (int b = 0; b < 128; b++) acc += g_cpart[b * 256 + j];
        g_c[j] = acc;
    }
    for (int t = blockIdx.x * blockDim.x + threadIdx.x; t < NW1 + NW2 + NWF;
         t += gridDim.x * blockDim.x) {
        if (t < NW1) {
            int i = t;
            int j = (i & 31) * 2, n = (i >> 5) & 63, kb = (i >> 11) & 3, kc = (i >> 13) & 7, l = i >> 16;
            int k = swzk(j, n);
            const float* s = W1s + (size_t)(l * 256 + kb * 64 + k) * 512 + kc * 64 + n;
            ((__half2*)g_W1ph)[i] = __floats2half2_rn(s[0], s[512]);
        } else if (t < NW1 + NW2) {
            int i = t - NW1;
            int j = (i & 31) * 2, n = (i >> 5) & 31, p = (i >> 10) & 7, kc = (i >> 13) & 7, l = i >> 16;
            int k = swzk(j, n);
            const float* s = W2s + (size_t)(l * 512 + kc * 64 + k) * 256 + p * 32 + n;
            ((__half2*)g_W2ph)[i] = __floats2half2_rn(s[0], s[256]);
        } else {
            int i = t - NW1 - NW2;
            int j = (i & 31) * 2, n = (i >> 5) & 255, c = i >> 13;
            int k = swzk(j, n);
            float v0, v1;
            if (c == 0) {
                v0 = 0.f; v1 = 0.f;
                if (k < 32) {
#pragma unroll
                    for (int q = 0; q < 4; q++) {
                        v0 += g_Apart[(k * 4 + q) * 256 + n];
                        v1 += g_Apart[((k + 1) * 4 + q) * 256 + n];
                    }
                }
            } else {
                const float* s = Wcat + (size_t)((c - 1) * 64 + k) * 256 + n;
                v0 = s[0]; v1 = s[256];
            }
            ((__half2*)g_Wfph)[i] = __floats2half2_rn(v0, v1);
        }
    }
}

// =====================================================================
// Persistent fused network kernel (fp16 operands, fp32 accum).
// One CTA = 64 rows, 256 threads, occ 2. Full 32KB weight buffers,
// 2 syncs per kc, loads fully overlapped with the opposite GEMM.
// =====================================================================
__global__ __launch_bounds__(256, 2) void fused_net(
    const float* __restrict__ xnum, const int* __restrict__ xidx,
    const float* __restrict__ cemb,
    const float* __restrict__ b1g, const float* __restrict__ b2g,
    const float* __restrict__ lng, const float* __restrict__ lnbet,
    const float* __restrict__ gf,  const float* __restrict__ betf,
    const float* __restrict__ Wh,  const float* __restrict__ bh,
    float* __restrict__ out)
{
    extern __shared__ float dsm[];
    __shared__ float red_s[64 * 4], red_q[64 * 4];
    __shared__ int s_xidx[64 * 16];
    uint32_t raw  = sm32(dsm);
    uint32_t base = (raw + 1023u) & ~1023u;
    const uint32_t LNB = base;
    const uint32_t TCH = base + 32768u;
    const uint32_t B0  = base + 40960u;
    const uint32_t B1  = base + 73728u;
    const uint32_t P0A = base;
    const uint32_t P0B = base + 16384u;

    int tid = threadIdx.x, wid = tid >> 5, lane = tid & 31;
    int bm = blockIdx.x * 64;
    int warp_m = wid & 1, warp_n = wid >> 1;
    int wm1 = wid & 3,    wn1 = wid >> 2;
    int lr = lane & 7, lh = (lane >> 3) & 1, lg = lane >> 4;

    float hreg[16][4];
#pragma unroll
    for (int t = 0; t < 16; t++)
#pragma unroll
        for (int q = 0; q < 4; q++) hreg[t][q] = 0.f;

    for (int i = tid; i < 64 * 16; i += 256) s_xidx[i] = xidx[bm * 16 + i];
    __syncthreads();

    // ================= Phase 0: first GEMM, 65 chunks of 64 k =================
    {
        int ar = tid >> 2, aq = tid & 3;
        float4 R4[4];
        auto ldgA = [&](int c) {
            if (c == 0) {
                if (aq < 2) {
                    const float4* s = (const float4*)(xnum + (size_t)(bm + ar) * 32 + aq * 16);
#pragma unroll
                    for (int i = 0; i < 4; i++) R4[i] = s[i];
                } else {
#pragma unroll
                    for (int i = 0; i < 4; i++) R4[i] = make_float4(0.f, 0.f, 0.f, 0.f);
                }
            } else {
                int cc = c - 1, f = cc >> 2, d0 = (cc & 3) << 6;
                const float4* s = (const float4*)(cemb + (size_t)s_xidx[ar * 16 + f] * 256 + d0 + aq * 16);
#pragma unroll
                for (int i = 0; i < 4; i++) R4[i] = s[i];
            }
        };
        auto stsA = [&](int b) {
            uint32_t bufa = P0A + (uint32_t)b * 8192u + (uint32_t)ar * 128u;
#pragma unroll
            for (int t = 0; t < 2; t++) {
                int g = aq * 2 + t;
                uint32_t a = bufa + (uint32_t)((g ^ (ar & 7)) << 4);
                st4s(a, f2h2(R4[2 * t].x, R4[2 * t].y), f2h2(R4[2 * t].z, R4[2 * t].w),
                        f2h2(R4[2 * t + 1].x, R4[2 * t + 1].y), f2h2(R4[2 * t + 1].z, R4[2 * t + 1].w));
            }
        };
        auto cpB = [&](int c, int b) {
            const float4* src = (const float4*)(g_Wfph + (size_t)c * 16384) + tid;
            uint32_t Bd = P0B + (uint32_t)b * 32768u + (uint32_t)tid * 16u;
#pragma unroll
            for (int i = 0; i < 8; i++) cpa16(Bd + (uint32_t)i * 4096u, src + i * 256);
            CPA_COMMIT();
        };

        ldgA(0);
        cpB(0, 0); cpB(1, 1);
#pragma unroll 1
        for (int c = 0; c <= 64; c++) {
            int b = c & 1;
            stsA(b);
            if (c < 64) ldgA(c + 1);
            if (c + 1 <= 64) CPA_WAIT(1); else CPA_WAIT(0);
            __syncthreads();
            uint32_t Ab = P0A + (uint32_t)b * 8192u;
            uint32_t Bb = P0B + (uint32_t)b * 32768u;
#pragma unroll
            for (int s = 0; s < 4; s++) {
                int g = s * 2 + lg;
                uint32_t af[2][4];
#pragma unroll
                for (int i = 0; i < 2; i++) {
                    int R = warp_m * 32 + i * 16 + lr + lh * 8;
                    ldm4(af[i], Ab + (uint32_t)(R * 128 + ((g ^ (R & 7)) << 4)));
                }
                uint32_t bf[8][2];
#pragma unroll
                for (int p = 0; p < 4; p++) {
                    int n = warp_n * 64 + p * 16 + lr + lh * 8;
                    uint32_t t4[4];
                    ldm4(t4, Bb + (uint32_t)(n * 128 + ((g ^ (n & 7)) << 4)));
                    bf[2 * p][0] = t4[0]; bf[2 * p][1] = t4[2];
                    bf[2 * p + 1][0] = t4[1]; bf[2 * p + 1][1] = t4[3];
                }
#pragma unroll
                for (int i = 0; i < 2; i++)
#pragma unroll
                    for (int j = 0; j < 8; j++)
                        mma_f16(hreg[i * 8 + j], af[i], bf[j][0], bf[j][1]);
            }
            __syncthreads();
            if (c + 2 <= 64) cpB(c + 2, b);
        }
#pragma unroll
        for (int i = 0; i < 2; i++)
#pragma unroll
            for (int j = 0; j < 8; j++) {
                int col = warp_n * 64 + j * 8 + (lane & 3) * 2;
                float b0 = g_c[col], b1 = g_c[col + 1];
                hreg[i * 8 + j][0] += b0; hreg[i * 8 + j][1] += b1;
                hreg[i * 8 + j][2] += b0; hreg[i * 8 + j][3] += b1;
            }
    }

    // ---- full 32KB weight loaders ----
    auto issueWf = [&](const __half* W, int kc, uint32_t B) {
        const float4* src = (const float4*)(W + (size_t)kc * 16384) + tid;
#pragma unroll
        for (int i = 0; i < 8; i++) cpa16(B + (uint32_t)(tid * 16 + i * 4096), src + i * 256);
        CPA_COMMIT();
    };

    // ---- LN from hreg -> LNB (fp16) ----
    auto do_ln = [&](const float* gam, const float* bet) {
        float rs_[4] = {0.f, 0.f, 0.f, 0.f}, rq_[4] = {0.f, 0.f, 0.f, 0.f};
#pragma unroll
        for (int i = 0; i < 2; i++)
#pragma unroll
            for (int j = 0; j < 8; j++) {
                float v0 = hreg[i * 8 + j][0], v1 = hreg[i * 8 + j][1];
                float v2 = hreg[i * 8 + j][2], v3 = hreg[i * 8 + j][3];
                rs_[i * 2 + 0] += v0 + v1;  rq_[i * 2 + 0] += v0 * v0 + v1 * v1;
                rs_[i * 2 + 1] += v2 + v3;  rq_[i * 2 + 1] += v2 * v2 + v3 * v3;
            }
#pragma unroll
        for (int t = 0; t < 4; t++)
#pragma unroll
            for (int o = 1; o <= 2; o <<= 1) {
                rs_[t] += __shfl_xor_sync(0xffffffffu, rs_[t], o);
                rq_[t] += __shfl_xor_sync(0xffffffffu, rq_[t], o);
            }
        if ((lane & 3) == 0) {
#pragma unroll
            for (int i = 0; i < 2; i++)
#pragma unroll
                for (int h = 0; h < 2; h++) {
                    int rloc = warp_m * 32 + i * 16 + h * 8 + (lane >> 2);
                    red_s[rloc * 4 + warp_n] = rs_[i * 2 + h];
                    red_q[rloc * 4 + warp_n] = rq_[i * 2 + h];
                }
        }
        __syncthreads();
#pragma unroll
        for (int i = 0; i < 2; i++)
#pragma unroll
            for (int h = 0; h < 2; h++) {
                int rloc = warp_m * 32 + i * 16 + h * 8 + (lane >> 2);
                float s = red_s[rloc * 4 + 0] + red_s[rloc * 4 + 1]
                        + red_s[rloc * 4 + 2] + red_s[rloc * 4 + 3];
                float q = red_q[rloc * 4 + 0] + red_q[rloc * 4 + 1]
                        + red_q[rloc * 4 + 2] + red_q[rloc * 4 + 3];
                float mu = s * (1.f / 256.f);
                float rinv = rsqrtf(q * (1.f / 256.f) - mu * mu + 1e-5f);
#pragma unroll
                for (int j = 0; j < 8; j++) {
                    int col = warp_n * 64 + j * 8 + (lane & 3) * 2;
                    float y0 = (hreg[i * 8 + j][h * 2 + 0] - mu) * rinv * gam[col]     + bet[col];
                    float y1 = (hreg[i * 8 + j][h * 2 + 1] - mu) * rinv * gam[col + 1] + bet[col + 1];
                    int kcol = col & 63, kb = col >> 6, gg = kcol >> 3;
                    uint32_t addr = LNB + (uint32_t)(kb * 8192 + rloc * 128
                                   + ((gg ^ (rloc & 7)) << 4) + (kcol & 7) * 2);
                    st1s(addr, f2h2(y0, y1));
                }
            }
        __syncthreads();
    };

    // GEMM1 full: 4 kb blocks from one 32KB buffer
    float a1[4][4];
    auto g1full = [&](uint32_t B) {
#pragma unroll
        for (int kb = 0; kb < 4; kb++) {
#pragma unroll
            for (int s = 0; s < 4; s++) {
                int g = s * 2 + lg;
                uint32_t af[4];
                int R = wm1 * 16 + lr + lh * 8;
                ldm4(af, LNB + (uint32_t)(kb * 8192 + R * 128 + ((g ^ (R & 7)) << 4)));
                uint32_t bf[4][2];
#pragma unroll
                for (int pp = 0; pp < 2; pp++) {
                    int n = wn1 * 32 + pp * 16 + lr + lh * 8;
                    uint32_t t4[4];
                    ldm4(t4, B + (uint32_t)(kb * 8192 + n * 128 + ((g ^ (n & 7)) << 4)));
                    bf[2 * pp][0] = t4[0]; bf[2 * pp][1] = t4[2];
                    bf[2 * pp + 1][0] = t4[1]; bf[2 * pp + 1][1] = t4[3];
                }
#pragma unroll
                for (int j = 0; j < 4; j++) mma_f16(a1[j], af, bf[j][0], bf[j][1]);
            }
        }
    };
    // GEMM2 full: A fragments hoisted out of the piece loop
    auto g2full = [&](uint32_t B) {
#pragma unroll
        for (int s = 0; s < 4; s++) {
            int g = s * 2 + lg;
            uint32_t af[2][4];
#pragma unroll
            for (int i = 0; i < 2; i++) {
                int R = warp_m * 32 + i * 16 + lr + lh * 8;
                ldm4(af[i], TCH + (uint32_t)(R * 128 + ((g ^ (R & 7)) << 4)));
            }
#pragma unroll
            for (int p = 0; p < 2; p++) {
                uint32_t Bp = B + (uint32_t)(2 * warp_n + p) * 4096u;
                uint32_t bf[4][2];
#pragma unroll
                for (int pp = 0; pp < 2; pp++) {
                    int nl = pp * 16 + lr + lh * 8;
                    uint32_t t4[4];
                    ldm4(t4, Bp + (uint32_t)(nl * 128 + ((g ^ (nl & 7)) << 4)));
                    bf[2 * pp][0] = t4[0]; bf[2 * pp][1] = t4[2];
                    bf[2 * pp + 1][0] = t4[1]; bf[2 * pp + 1][1] = t4[3];
                }
#pragma unroll
                for (int i = 0; i < 2; i++)
#pragma unroll
                    for (int jj = 0; jj < 4; jj++)
                        mma_f16(hreg[i * 8 + p * 4 + jj], af[i], bf[jj][0], bf[jj][1]);
            }
        }
    };

    issueWf(g_W1ph, 0, B0);

    // ================= 8 residual layers =================
#pragma unroll 1
    for (int l = 0; l < 8; l++) {
        do_ln(lng + l * 256, lnbet + l * 256);
        const __half* W1 = g_W1ph + (size_t)l * 8 * 16384;
        const __half* W2 = g_W2ph + (size_t)l * 8 * 16384;
        const float*  b1 = b1g + l * 512;
#pragma unroll 1
        for (int kc = 0; kc < 8; kc++) {
#pragma unroll
            for (int j = 0; j < 4; j++)
#pragma unroll
                for (int q = 0; q < 4; q++) a1[j][q] = 0.f;
            // ---- S1: wait W1(kc); issue W2(kc)->B1; GEMM1; relu+bias -> TCH ----
            CPA_WAIT(0);
            __syncthreads();
            issueWf(W2, kc, B1);
            g1full(B0);
#pragma unroll
            for (int j = 0; j < 4; j++) {
                int row0 = wm1 * 16 + (lane >> 2);
                int colL = wn1 * 32 + j * 8 + (lane & 3) * 2;
                int gc = kc * 64 + colL;
                float bb0 = b1[gc], bb1 = b1[gc + 1];
                uint32_t plo = f2h2(fmaxf(a1[j][0] + bb0, 0.f), fmaxf(a1[j][1] + bb1, 0.f));
                uint32_t phi = f2h2(fmaxf(a1[j][2] + bb0, 0.f), fmaxf(a1[j][3] + bb1, 0.f));
                int gg = colL >> 3;
                uint32_t sw = (uint32_t)(((gg ^ (row0 & 7)) << 4) + (colL & 7) * 2);
                st1s(TCH + (uint32_t)(row0 * 128) + sw, plo);
                st1s(TCH + (uint32_t)((row0 + 8) * 128) + sw, phi);
            }
            // ---- S2: wait W2(kc); issue W1(kc+1)->B0; GEMM2 ----
            CPA_WAIT(0);
            __syncthreads();
            if (kc < 7)     issueWf(W1, kc + 1, B0);
            else if (l < 7) issueWf(g_W1ph + (size_t)(l + 1) * 8 * 16384, 0, B0);
            g2full(B1);
        }
        const float* b2 = b2g + l * 256;
#pragma unroll
        for (int i = 0; i < 2; i++)
#pragma unroll
            for (int j = 0; j < 8; j++) {
                int col = warp_n * 64 + j * 8 + (lane & 3) * 2;
                float b0 = b2[col], b1v = b2[col + 1];
                hreg[i * 8 + j][0] += b0;  hreg[i * 8 + j][1] += b1v;
                hreg[i * 8 + j][2] += b0;  hreg[i * 8 + j][3] += b1v;
            }
    }

    // ================= final LN + head =================
    {
        float rs_[4] = {0.f, 0.f, 0.f, 0.f}, rq_[4] = {0.f, 0.f, 0.f, 0.f};
#pragma unroll
        for (int i = 0; i < 2; i++)
#pragma unroll
            for (int j = 0; j < 8; j++) {
                float v0 = hreg[i * 8 + j][0], v1 = hreg[i * 8 + j][1];
                float v2 = hreg[i * 8 + j][2], v3 = hreg[i * 8 + j][3];
                rs_[i * 2 + 0] += v0 + v1;  rq_[i * 2 + 0] += v0 * v0 + v1 * v1;
                rs_[i * 2 + 1] += v2 + v3;  rq_[i * 2 + 1] += v2 * v2 + v3 * v3;
            }
#pragma unroll
        for (int t = 0; t < 4; t++)
#pragma unroll
            for (int o = 1; o <= 2; o <<= 1) {
                rs_[t] += __shfl_xor_sync(0xffffffffu, rs_[t], o);
                rq_[t] += __shfl_xor_sync(0xffffffffu, rq_[t], o);
            }
        if ((lane & 3) == 0) {
#pragma unroll
            for (int i = 0; i < 2; i++)
#pragma unroll
                for (int h = 0; h < 2; h++) {
                    int rloc = warp_m * 32 + i * 16 + h * 8 + (lane >> 2);
                    red_s[rloc * 4 + warp_n] = rs_[i * 2 + h];
                    red_q[rloc * 4 + warp_n] = rq_[i * 2 + h];
                }
        }
        __syncthreads();
        float hd0[4] = {0.f, 0.f, 0.f, 0.f}, hd1[4] = {0.f, 0.f, 0.f, 0.f};
#pragma unroll
        for (int i = 0; i < 2; i++)
#pragma unroll
            for (int h = 0; h < 2; h++) {
                int rloc = warp_m * 32 + i * 16 + h * 8 + (lane >> 2);
                float s = red_s[rloc * 4 + 0] + red_s[rloc * 4 + 1]
                        + red_s[rloc * 4 + 2] + red_s[rloc * 4 + 3];
                float q = red_q[rloc * 4 + 0] + red_q[rloc * 4 + 1]
                        + red_q[rloc * 4 + 2] + red_q[rloc * 4 + 3];
                float mu = s * (1.f / 256.f);
                float rinv = rsqrtf(q * (1.f / 256.f) - mu * mu + 1e-5f);
#pragma unroll
                for (int j = 0; j < 8; j++) {
                    int col = warp_n * 64 + j * 8 + (lane & 3) * 2;
                    float y0 = (hreg[i * 8 + j][h * 2 + 0] - mu) * rinv * gf[col]     + betf[col];
                    float y1 = (hreg[i * 8 + j][h * 2 + 1] - mu) * rinv * gf[col + 1] + betf[col + 1];
                    hd0[i * 2 + h] += y0 * Wh[col * 2 + 0] + y1 * Wh[col * 2 + 2];
                    hd1[i * 2 + h] += y0 * Wh[col * 2 + 1] + y1 * Wh[col * 2 + 3];
                }
            }
#pragma unroll
        for (int t = 0; t < 4; t++)
#pragma unroll
            for (int o = 1; o <= 2; o <<= 1) {
                hd0[t] += __shfl_xor_sync(0xffffffffu, hd0[t], o);
                hd1[t] += __shfl_xor_sync(0xffffffffu, hd1[t], o);
            }
        __syncthreads();
        if ((lane & 3) == 0) {
#pragma unroll
            for (int i = 0; i < 2; i++)
#pragma unroll
                for (int h = 0; h < 2; h++) {
                    int rloc = warp_m * 32 + i * 16 + h * 8 + (lane >> 2);
                    red_s[rloc * 4 + warp_n] = hd0[i * 2 + h];
                    red_q[rloc * 4 + warp_n] = hd1[i * 2 + h];
                }
        }
        __syncthreads();
        if (tid < 64) {
            float s0 = red_s[tid * 4 + 0] + red_s[tid * 4 + 1]
                     + red_s[tid * 4 + 2] + red_s[tid * 4 + 3];
            float s1 = red_q[tid * 4 + 0] + red_q[tid * 4 + 1]
                     + red_q[tid * 4 + 2] + red_q[tid * 4 + 3];
            out[(bm + tid) * 2 + 0] = s0 + bh[0];
            out[(bm + tid) * 2 + 1] = s1 + bh[1];
        }
    }
}

// ---------------- launch (3 kernels) ----------------
extern "C" void kernel_launch(void* const* d_in, const int* in_sizes, int n_in,
                              void* d_out, int out_size) {
    const float* x_num   = (const float*)d_in[0];
    const int*   xidx    = (const int*)  d_in[1];
    const float* w_num   = (const float*)d_in[2];
    const float* b_num   = (const float*)d_in[3];
    const float* cat_emb = (const float*)d_in[4];
    const float* W_first = (const float*)d_in[5];
    const float* b_first = (const float*)d_in[6];
    const float* ln_g    = (const float*)d_in[7];
    const float* ln_b    = (const float*)d_in[8];
    const float* W1s     = (const float*)d_in[9];
    const float* b1s     = (const float*)d_in[10];
    const float* W2s     = (const float*)d_in[11];
    const float* b2s     = (const float*)d_in[12];
    const float* g_f     = (const float*)d_in[13];
    const float* beta_f  = (const float*)d_in[14];
    const float* W_head  = (const float*)d_in[15];
    const float* b_head  = (const float*)d_in[16];

    cudaFuncSetAttribute(fused_net, cudaFuncAttributeMaxDynamicSharedMemorySize, SMEM_DYN);

    prep_fold<<<256, 256>>>(w_num, b_num, W_first);
    pack_all<<<1024, 256>>>(W1s, W2s, W_first + (size_t)8192 * 256, b_first);

    fused_net<<<256, 256, SMEM_DYN>>>(
        x_num, xidx, cat_emb, b1s, b2s, ln_g, ln_b,
        g_f, beta_f, W_head, b_head, (float*)d_out);
}